// round 14
// baseline (speedup 1.0000x reference)
#include <cuda_runtime.h>
#include <cuda_fp16.h>
#include <cstdint>

#define N_ROWS   16384
#define N_CODES  8192
#define DIM      64
#define BM       128
#define BN       64
#define NCHUNK   (N_CODES / BN)      // 128
#define THREADS  256
#define ROWB     144                  // 9*16B; 9 mod 8 = 1 -> conflict-free LDSM
#define CGSTRIDE (16 * ROWB)
#define BSTG     (BN * ROWB)          // 9216 B per B stage
#define NSTAGE   3
#define QSLOTS   48
#define NARG     (N_ROWS / BM)        // 128 argmin CTAs
#define NZERO    128
#define DISC_F4  ((size_t)N_ROWS * N_CODES / 4)

// smem offsets
#define OFF_A    0
#define OFF_B    18432                 // 3 * 9216 = 27648
#define OFF_Q    46080                 // 256 * 48 * 4 = 49152
#define OFF_RED  95232                 // 128 * 8
#define OFF_XN   96256                 // 128 * 4
#define OFF_SEED 96768                 // 128 * 4
#define SMEMSZ   97280                 // x2 = 194560 < 228KB

// device scratch
__device__ __align__(16) __half g_cbh[(size_t)N_CODES * DIM];  // fp16 hi only
__device__ __align__(16) float  g_cnorm[N_CODES];
__device__ unsigned g_cmax_u;
__device__ int g_idx[N_ROWS];

// ---------------- helpers ----------------
__device__ __forceinline__ uint32_t h2_as_u32(__half2 h) {
    uint32_t u; __builtin_memcpy(&u, &h, 4); return u;
}
__device__ __forceinline__ uint32_t pack_h2(__half a, __half b) {
    return h2_as_u32(__halves2half2(a, b));
}
__device__ __forceinline__ uint32_t smem_u32(const void* p) {
    uint32_t a;
    asm("{ .reg .u64 t; cvta.to.shared.u64 t, %1; cvt.u32.u64 %0, t; }" : "=r"(a) : "l"(p));
    return a;
}
__device__ __forceinline__ unsigned ord_f32(float f) {
    unsigned u = __float_as_uint(f);
    return (u & 0x80000000u) ? ~u : (u | 0x80000000u);
}
#define CPA16(d,s)   asm volatile("cp.async.cg.shared.global [%0], [%1], 16;" :: "r"(d), "l"(s) : "memory")
#define CPA_COMMIT() asm volatile("cp.async.commit_group;" ::: "memory")
#define CPA_WAIT1()  asm volatile("cp.async.wait_group 1;" ::: "memory")

#define LDM_X4(r0,r1,r2,r3,a) \
    asm volatile("ldmatrix.sync.aligned.m8n8.x4.shared.b16 {%0,%1,%2,%3}, [%4];" \
                 : "=r"(r0), "=r"(r1), "=r"(r2), "=r"(r3) : "r"(a))

__device__ __forceinline__ void mma16816(float* d, const uint32_t* a,
                                         uint32_t b0, uint32_t b1) {
    asm volatile("mma.sync.aligned.m16n8k16.row.col.f32.f16.f16.f32 "
                 "{%0,%1,%2,%3}, {%4,%5,%6,%7}, {%8,%9}, {%0,%1,%2,%3};"
                 : "+f"(d[0]), "+f"(d[1]), "+f"(d[2]), "+f"(d[3])
                 : "r"(a[0]), "r"(a[1]), "r"(a[2]), "r"(a[3]), "r"(b0), "r"(b1));
}

// branch-free candidate push: compare with OLD th, predicated STS, then tighten
__device__ __forceinline__ void push_cand(uint32_t qb, int& qn, float d,
                                          float& th, float m2, uint32_t entry) {
    uint32_t addr = qb + ((uint32_t)qn << 10);   // slot stride 256 words
    int take;
    asm volatile("{ .reg .pred p; setp.le.f32 p, %1, %2; "
                 "@p st.shared.b32 [%3], %4; selp.b32 %0, 1, 0, p; }"
                 : "=r"(take) : "f"(d), "f"(th), "r"(addr), "r"(entry) : "memory");
    qn += take;
    th = fminf(th, d + m2);
}

// ---------------------------------------------------------------------------
__global__ void init_kernel() { g_cmax_u = 0u; }

__global__ void prep_kernel(const float* __restrict__ cb) {
    int g = blockIdx.x * blockDim.x + threadIdx.x;
    int code = g >> 5, lane = g & 31;
    float2 v = reinterpret_cast<const float2*>(cb + (size_t)code * DIM)[lane];
    __half2* dst = reinterpret_cast<__half2*>(g_cbh + (size_t)code * DIM);
    dst[lane] = __halves2half2(__float2half_rn(v.x), __float2half_rn(v.y));
    float s = v.x * v.x + v.y * v.y;
#pragma unroll
    for (int o = 16; o; o >>= 1) s += __shfl_xor_sync(~0u, s, o);
    if (lane == 0) {
        g_cnorm[code] = s;
        atomicMax(&g_cmax_u, __float_as_uint(s));
    }
}

// exact fp32 rescore of one queue entry
__device__ __forceinline__ void rescore(uint32_t e, int row0,
                                        const float* __restrict__ x,
                                        const float* __restrict__ cb,
                                        unsigned long long* red) {
    int rl = e >> 13;
    int col = e & 8191;
    const float4* xr = reinterpret_cast<const float4*>(x + (size_t)(row0 + rl) * DIM);
    const float4* cr = reinterpret_cast<const float4*>(cb + (size_t)col * DIM);
    float s = 0.f;
#pragma unroll
    for (int i = 0; i < 16; i++) {
        float4 a = __ldg(xr + i), b = __ldg(cr + i);
        s = fmaf(a.x, b.x, s); s = fmaf(a.y, b.y, s);
        s = fmaf(a.z, b.z, s); s = fmaf(a.w, b.w, s);
    }
    float dist = fmaf(-2.f, s, __ldg(&g_cnorm[col]));
    unsigned long long key = ((unsigned long long)ord_f32(dist) << 32) | (unsigned)col;
    atomicMin(&red[rl], key);
}

// ---------------------------------------------------------------------------
// Fused: bid < NARG -> single-pass fp16 approx scan (seeded threshold,
//        branch-free private queues, ballot-gated drains) + exact rescore;
//        bid >= NARG -> zerofill the one-hot output.
// ---------------------------------------------------------------------------
__global__ void __launch_bounds__(THREADS, 2)
argmin_fused(const float* __restrict__ x, const float* __restrict__ cb,
             float* __restrict__ out_disc) {
    const int tid = threadIdx.x;

    if (blockIdx.x >= NARG) {
        size_t i = (size_t)(blockIdx.x - NARG) * THREADS + tid;
        const size_t stride = (size_t)NZERO * THREADS;
        float4 z = make_float4(0.f, 0.f, 0.f, 0.f);
        float4* o = reinterpret_cast<float4*>(out_disc);
#pragma unroll 4
        for (; i < DISC_F4; i += stride) __stcs(o + i, z);
        return;
    }

    extern __shared__ char smem[];
    const uint32_t Sb = smem_u32(smem);
    const uint32_t As = Sb + OFF_A;
    const uint32_t Bs = Sb + OFF_B;
    unsigned long long* red = reinterpret_cast<unsigned long long*>(smem + OFF_RED);
    float* xn = reinterpret_cast<float*>(smem + OFF_XN);
    float* seed = reinterpret_cast<float*>(smem + OFF_SEED);
    uint32_t* qsl = reinterpret_cast<uint32_t*>(smem + OFF_Q) + tid;  // entry i at [i*256]
    const uint32_t qb = Sb + OFF_Q + tid * 4;
    int qn = 0;

    const int wid = tid >> 5, lane = tid & 31;
    const int row0 = blockIdx.x * BM;
    const int r0l = wid * 16 + (lane >> 2);
    const int r1l = r0l + 8;

    if (tid < BM) xn[tid] = 0.f;
    __syncthreads();

    // ---- stage A (fp16 hi) + row norms ----
    for (int t = tid; t < BM * (DIM / 4); t += THREADS) {
        int row = t >> 4, q = t & 15;
        float4 v = reinterpret_cast<const float4*>(x)[(size_t)(row0 + row) * 16 + q];
        uint32_t hp0 = pack_h2(__float2half_rn(v.x), __float2half_rn(v.y));
        uint32_t hp1 = pack_h2(__float2half_rn(v.z), __float2half_rn(v.w));
        uint32_t base = As + row * ROWB + q * 8;
        asm volatile("st.shared.v2.b32 [%0], {%1,%2};" :: "r"(base), "r"(hp0), "r"(hp1));
        float p = v.x * v.x + v.y * v.y + v.z * v.z + v.w * v.w;
        atomicAdd(&xn[row], p);
    }

    // ---- seed: exact distance to code 0 per row (kills cold-start flood) ----
    if (tid < BM) {
        const float4* xr = reinterpret_cast<const float4*>(x + (size_t)(row0 + tid) * DIM);
        const float4* cr = reinterpret_cast<const float4*>(cb);
        float s = 0.f;
#pragma unroll
        for (int i = 0; i < 16; i++) {
            float4 a = __ldg(xr + i), b = __ldg(cr + i);
            s = fmaf(a.x, b.x, s); s = fmaf(a.y, b.y, s);
            s = fmaf(a.z, b.z, s); s = fmaf(a.w, b.w, s);
        }
        float dist = fmaf(-2.f, s, __ldg(&g_cnorm[0]));
        seed[tid] = dist;
        red[tid] = ((unsigned long long)ord_f32(dist) << 32);   // code 0
    }
    __syncthreads();

    // margins (validated rel_err 0.0 in R11-R13)
    const float cmaxf = sqrtf(__uint_as_float(g_cmax_u));
    const float m2_0 = 2.f * (ldexpf(sqrtf(xn[r0l]) * cmaxf, -9) * 1.1f + 1e-3f);
    const float m2_1 = 2.f * (ldexpf(sqrtf(xn[r1l]) * cmaxf, -9) * 1.1f + 1e-3f);
    float th0 = seed[r0l] + m2_0;
    float th1 = seed[r1l] + m2_1;

    // ---- persistent A fragments: 4 kgroups (xh only) ----
    uint32_t afr[4][4];
    {
        int t = lane >> 3;
        int arow = wid * 16 + ((t & 1) << 3) + (lane & 7);
        uint32_t abase = As + arow * ROWB + ((t >> 1) << 4);
#pragma unroll
        for (int kg = 0; kg < 4; kg++)
            LDM_X4(afr[kg][0], afr[kg][1], afr[kg][2], afr[kg][3], abase + kg * 32);
    }
    __syncthreads();

    const uint32_t bl0 = Bs + (((lane >> 4) << 3) + (lane & 7)) * ROWB
                       + ((lane >> 3) & 1) * 16;

    // ---- prologue: prefetch chunks 0 and 1 ----
    {
        int code = tid >> 3, off = (tid & 7) * 16;
        CPA16(Bs + code * ROWB + off, (const char*)g_cbh + ((size_t)code * 128 + off));
        {
            int i2 = tid + THREADS;
            int c2 = i2 >> 3, o2 = (i2 & 7) * 16;
            CPA16(Bs + c2 * ROWB + o2, (const char*)g_cbh + ((size_t)c2 * 128 + o2));
        }
        CPA_COMMIT();
        CPA16(Bs + BSTG + code * ROWB + off,
              (const char*)g_cbh + (size_t)BN * 128 + (size_t)code * 128 + off);
        {
            int i2 = tid + THREADS;
            int c2 = i2 >> 3, o2 = (i2 & 7) * 16;
            CPA16(Bs + BSTG + c2 * ROWB + o2,
                  (const char*)g_cbh + (size_t)BN * 128 + (size_t)c2 * 128 + o2);
        }
        CPA_COMMIT();
    }

    int bc = 0, bn = 2;   // current buffer, next-issue buffer
    for (int c = 0; c < NCHUNK; c++) {
        CPA_WAIT1();          // completes group c (one group stays in flight)
        __syncthreads();      // all warps done reading the buffer we overwrite

        if (c + 2 < NCHUNK) {
            const char* src = (const char*)g_cbh + (size_t)(c + 2) * BN * 128;
            uint32_t dbuf = Bs + bn * BSTG;
#pragma unroll
            for (int j = 0; j < 2; j++) {
                int i = tid + j * THREADS;
                int code = i >> 3, off = (i & 7) * 16;
                CPA16(dbuf + code * ROWB + off, src + (size_t)code * 128 + off);
            }
        }
        CPA_COMMIT();         // always commit (keeps group count uniform)

        // ballot-gated drain (warp-uniform, no block barrier needed)
        if (__any_sync(0xffffffffu, qn > 16)) {
            for (int i = 0; i < qn; i++) rescore(qsl[i * THREADS], row0, x, cb, red);
            qn = 0;
        }

        const uint32_t bb = bl0 + bc * BSTG;
        float acc[8][4];
#pragma unroll
        for (int f = 0; f < 8; f++)
#pragma unroll
            for (int j = 0; j < 4; j++) acc[f][j] = 0.f;

#pragma unroll
        for (int kg = 0; kg < 4; kg++) {
            uint32_t b[4][4];
#pragma unroll
            for (int cg = 0; cg < 4; cg++)
                LDM_X4(b[cg][0], b[cg][1], b[cg][2], b[cg][3],
                       bb + cg * CGSTRIDE + kg * 32);
#pragma unroll
            for (int cg = 0; cg < 4; cg++) {
                mma16816(acc[2 * cg],     afr[kg], b[cg][0], b[cg][1]);
                mma16816(acc[2 * cg + 1], afr[kg], b[cg][2], b[cg][3]);
            }
        }

        // branch-free epilogue
        int cbase = c * BN + ((lane & 3) << 1);
        uint32_t e0 = (uint32_t)((r0l << 13) | cbase);
        uint32_t e1 = (uint32_t)((r1l << 13) | cbase);
#pragma unroll
        for (int f = 0; f < 8; f++) {
            int col = cbase + f * 8;
            float cn0 = __ldg(&g_cnorm[col]);
            float cn1 = __ldg(&g_cnorm[col + 1]);
            float d0 = fmaf(-2.f, acc[f][0], cn0);
            float d1 = fmaf(-2.f, acc[f][1], cn1);
            float d2 = fmaf(-2.f, acc[f][2], cn0);
            float d3 = fmaf(-2.f, acc[f][3], cn1);
            push_cand(qb, qn, d0, th0, m2_0, e0 + f * 8);
            push_cand(qb, qn, d1, th0, m2_0, e0 + f * 8 + 1);
            push_cand(qb, qn, d2, th1, m2_1, e1 + f * 8);
            push_cand(qb, qn, d3, th1, m2_1, e1 + f * 8 + 1);
        }

        bc = (bc + 1 == NSTAGE) ? 0 : bc + 1;
        bn = (bn + 1 == NSTAGE) ? 0 : bn + 1;
    }

    // ---- final drain + index write ----
    for (int i = 0; i < qn; i++) rescore(qsl[i * THREADS], row0, x, cb, red);
    __syncthreads();
    if (tid < BM) g_idx[row0 + tid] = (int)(red[tid] & 0xffffffffu);
}

// ---------------------------------------------------------------------------
// Finalize: gather quantized rows + scatter the 1.0s into the one-hot.
// ---------------------------------------------------------------------------
__global__ void finalize_kernel(const float* __restrict__ cb,
                                float* __restrict__ out_disc,
                                float* __restrict__ outq) {
    unsigned i = blockIdx.x * 256u + threadIdx.x;
    unsigned n = i >> 4;
    unsigned c4 = i & 15u;
    int k = __ldg(&g_idx[n]);
    reinterpret_cast<float4*>(outq)[i] =
        reinterpret_cast<const float4*>(cb + (size_t)k * DIM)[c4];
    if (c4 == 0) out_disc[(size_t)n * N_CODES + k] = 1.0f;
}

// ---------------------------------------------------------------------------
extern "C" void kernel_launch(void* const* d_in, const int* in_sizes, int n_in,
                              void* d_out, int out_size) {
    const float* x  = (const float*)d_in[0];
    const float* cb = (const float*)d_in[1];
    float* out      = (float*)d_out;
    float* out_disc = out;
    float* out_q    = out + (size_t)N_ROWS * N_CODES;

    cudaFuncSetAttribute(argmin_fused, cudaFuncAttributeMaxDynamicSharedMemorySize, SMEMSZ);

    init_kernel<<<1, 1>>>();
    prep_kernel<<<(N_CODES * 32) / 256, 256>>>(cb);
    argmin_fused<<<NARG + NZERO, THREADS, SMEMSZ>>>(x, cb, out_disc);
    finalize_kernel<<<(N_ROWS * (DIM / 4)) / 256, 256>>>(cb, out_disc, out_q);
}

// round 15
// speedup vs baseline: 1.4617x; 1.4617x over previous
#include <cuda_runtime.h>
#include <cuda_fp16.h>
#include <cstdint>

#define N_ROWS   16384
#define N_CODES  8192
#define DIM      64
#define BM       128
#define BN       64
#define NCHUNK   (N_CODES / BN)      // 128
#define THREADS  256
#define ROWB     272                  // 17*16B; 17 mod 8 = 1 -> conflict-free LDSM
#define CGSTRIDE (16 * ROWB)
#define BBUF     (BN * ROWB)          // 17408 B per B stage
#define NARG     (N_ROWS / BM)        // 128 argmin CTAs
#define NZERO    128                  // zerofill CTAs
#define DISC_F4  ((size_t)N_ROWS * N_CODES / 4)
#define OFF_IDX  (BM * ROWB + 2 * BBUF)          // 69632
#define SMEMSZ   (OFF_IDX + BM * 4)              // 70144 (x2 = 140288 < 228KB)

// device scratch: [ch(128B) | cl(128B)] per code
__device__ __align__(16) __half g_cbe[(size_t)N_CODES * 128];
__device__ __align__(16) float  g_cnorm[N_CODES];
__device__ int g_idx[N_ROWS];

// ---------------- helpers ----------------
__device__ __forceinline__ uint32_t h2_as_u32(__half2 h) {
    uint32_t u;
    __builtin_memcpy(&u, &h, 4);
    return u;
}
__device__ __forceinline__ uint32_t pack_h2(__half a, __half b) {
    return h2_as_u32(__halves2half2(a, b));
}
__device__ __forceinline__ uint32_t smem_u32(const void* p) {
    uint32_t a;
    asm("{ .reg .u64 t; cvta.to.shared.u64 t, %1; cvt.u32.u64 %0, t; }" : "=r"(a) : "l"(p));
    return a;
}
#define CPA16(d,s)   asm volatile("cp.async.cg.shared.global [%0], [%1], 16;" :: "r"(d), "l"(s) : "memory")
#define CPA_COMMIT() asm volatile("cp.async.commit_group;" ::: "memory")
#define CPA_WAIT0()  asm volatile("cp.async.wait_group 0;" ::: "memory")

#define LDM_X4(r0,r1,r2,r3,a) \
    asm volatile("ldmatrix.sync.aligned.m8n8.x4.shared.b16 {%0,%1,%2,%3}, [%4];" \
                 : "=r"(r0), "=r"(r1), "=r"(r2), "=r"(r3) : "r"(a))

__device__ __forceinline__ void mma16816(float* d, const uint32_t* a,
                                         uint32_t b0, uint32_t b1) {
    asm volatile("mma.sync.aligned.m16n8k16.row.col.f32.f16.f16.f32 "
                 "{%0,%1,%2,%3}, {%4,%5,%6,%7}, {%8,%9}, {%0,%1,%2,%3};"
                 : "+f"(d[0]), "+f"(d[1]), "+f"(d[2]), "+f"(d[3])
                 : "r"(a[0]), "r"(a[1]), "r"(a[2]), "r"(a[3]), "r"(b0), "r"(b1));
}

// ---------------------------------------------------------------------------
// Prep: codebook -> fp16 [ch|cl] + squared norms. One warp per code.
// ---------------------------------------------------------------------------
__global__ void prep_kernel(const float* __restrict__ cb) {
    int g = blockIdx.x * blockDim.x + threadIdx.x;
    int code = g >> 5, lane = g & 31;
    float2 v = reinterpret_cast<const float2*>(cb + (size_t)code * DIM)[lane];
    __half hx = __float2half_rn(v.x), hy = __float2half_rn(v.y);
    float lx = v.x - __half2float(hx), ly = v.y - __half2float(hy);
    __half2* dst = reinterpret_cast<__half2*>(g_cbe + (size_t)code * 128);
    dst[lane]      = __halves2half2(hx, hy);
    dst[32 + lane] = __halves2half2(__float2half_rn(lx), __float2half_rn(ly));
    float s = v.x * v.x + v.y * v.y;
#pragma unroll
    for (int o = 16; o; o >>= 1) s += __shfl_xor_sync(~0u, s, o);
    if (lane == 0) g_cnorm[code] = s;
}

// ---------------------------------------------------------------------------
// Fused: bid < NARG -> 8-warp mma.sync distance GEMM + argmin (R9 hot loop,
//        unchanged) + in-CTA gather of quantized rows;
//        bid >= NARG -> stream zeros into the one-hot output.
// dot = xh.ch + xl.ch + xh.cl ; ch fragments reused for passes 1+2.
// ---------------------------------------------------------------------------
__global__ void __launch_bounds__(THREADS, 1)
argmin_fused(const float* __restrict__ x, const float* __restrict__ cb,
             float* __restrict__ out_disc, float* __restrict__ out_q) {
    const int tid = threadIdx.x;

    if (blockIdx.x >= NARG) {
        size_t i = (size_t)(blockIdx.x - NARG) * THREADS + tid;
        const size_t stride = (size_t)NZERO * THREADS;
        float4 z = make_float4(0.f, 0.f, 0.f, 0.f);
        float4* o = reinterpret_cast<float4*>(out_disc);
#pragma unroll 4
        for (; i < DISC_F4; i += stride) __stcs(o + i, z);
        return;
    }

    extern __shared__ char smem[];
    const uint32_t As = smem_u32(smem);                 // [128][272] : [xh|xl]
    const uint32_t Bs = As + BM * ROWB;                 // B ring [2][17408]
    int* idxs = reinterpret_cast<int*>(smem + OFF_IDX); // [128] final indices

    const int wid = tid >> 5, lane = tid & 31;
    const int row0 = blockIdx.x * BM;

    // ---- Build A staging: row = [xh(128B) | xl(128B)] ----
    for (int t = tid; t < BM * (DIM / 4); t += THREADS) {
        int row = t >> 4, q = t & 15;
        float4 v = reinterpret_cast<const float4*>(x)[(size_t)(row0 + row) * 16 + q];
        __half h0 = __float2half_rn(v.x), h1 = __float2half_rn(v.y);
        __half h2 = __float2half_rn(v.z), h3 = __float2half_rn(v.w);
        uint32_t hp0 = pack_h2(h0, h1);
        uint32_t hp1 = pack_h2(h2, h3);
        uint32_t lp0 = pack_h2(__float2half_rn(v.x - __half2float(h0)),
                               __float2half_rn(v.y - __half2float(h1)));
        uint32_t lp1 = pack_h2(__float2half_rn(v.z - __half2float(h2)),
                               __float2half_rn(v.w - __half2float(h3)));
        uint32_t base = As + row * ROWB + q * 8;
        asm volatile("st.shared.v2.b32 [%0], {%1,%2};" :: "r"(base), "r"(hp0), "r"(hp1));
        asm volatile("st.shared.v2.b32 [%0], {%1,%2};" :: "r"(base + 128), "r"(lp0), "r"(lp1));
    }
    __syncthreads();

    // ---- Persistent A fragments: kgroups 0-3 = xh, 4-7 = xl ----
    uint32_t afr[8][4];
    {
        int t = lane >> 3;
        int arow = wid * 16 + ((t & 1) << 3) + (lane & 7);
        uint32_t abase = As + arow * ROWB + ((t >> 1) << 4);
#pragma unroll
        for (int kg = 0; kg < 8; kg++)
            LDM_X4(afr[kg][0], afr[kg][1], afr[kg][2], afr[kg][3], abase + kg * 32);
    }
    __syncthreads();

    // per-lane B ldmatrix base (16 codes x 16 k per LDM_X4)
    const uint32_t bl0 = Bs + (((lane >> 4) << 3) + (lane & 7)) * ROWB
                       + ((lane >> 3) & 1) * 16;

    // ---- prefetch chunk 0: 64 codes x 256B = 1024 x 16B ops, 4 per thread ----
    {
#pragma unroll
        for (int j = 0; j < 4; j++) {
            int i = tid + j * THREADS;
            int code = i >> 4, off = (i & 15) * 16;
            CPA16(Bs + code * ROWB + off, (const char*)g_cbe + i * 16);
        }
        CPA_COMMIT();
    }

    float best0 = 3.4e38f, best1 = 3.4e38f;
    int idx0 = 0, idx1 = 0;

    for (int c = 0; c < NCHUNK; c++) {
        CPA_WAIT0();
        __syncthreads();
        if (c + 1 < NCHUNK) {
            const char* src = (const char*)g_cbe + (size_t)(c + 1) * BN * 256;
            uint32_t dbuf = Bs + ((c + 1) & 1) * BBUF;
#pragma unroll
            for (int j = 0; j < 4; j++) {
                int i = tid + j * THREADS;
                int code = i >> 4, off = (i & 15) * 16;
                CPA16(dbuf + code * ROWB + off, src + i * 16);
            }
            CPA_COMMIT();
        }

        const uint32_t bb = bl0 + (c & 1) * BBUF;
        float acc[8][4];
#pragma unroll
        for (int f = 0; f < 8; f++)
#pragma unroll
            for (int j = 0; j < 4; j++) acc[f][j] = 0.f;

        // passes 1+2: per kgroup, load ch frags (4 LDM), sweep acc0..7 twice
#pragma unroll
        for (int t = 0; t < 4; t++) {
            uint32_t b[4][4];
#pragma unroll
            for (int cg = 0; cg < 4; cg++)
                LDM_X4(b[cg][0], b[cg][1], b[cg][2], b[cg][3],
                       bb + cg * CGSTRIDE + t * 32);
#pragma unroll
            for (int cg = 0; cg < 4; cg++) {
                mma16816(acc[2 * cg],     afr[t], b[cg][0], b[cg][1]);
                mma16816(acc[2 * cg + 1], afr[t], b[cg][2], b[cg][3]);
            }
#pragma unroll
            for (int cg = 0; cg < 4; cg++) {
                mma16816(acc[2 * cg],     afr[4 + t], b[cg][0], b[cg][1]);
                mma16816(acc[2 * cg + 1], afr[4 + t], b[cg][2], b[cg][3]);
            }
        }
        // pass 3: xh . cl
#pragma unroll
        for (int t = 0; t < 4; t++) {
            uint32_t b[4][4];
#pragma unroll
            for (int cg = 0; cg < 4; cg++)
                LDM_X4(b[cg][0], b[cg][1], b[cg][2], b[cg][3],
                       bb + 128 + cg * CGSTRIDE + t * 32);
#pragma unroll
            for (int cg = 0; cg < 4; cg++) {
                mma16816(acc[2 * cg],     afr[t], b[cg][0], b[cg][1]);
                mma16816(acc[2 * cg + 1], afr[t], b[cg][2], b[cg][3]);
            }
        }

        int base = c * BN + ((lane & 3) << 1);
#pragma unroll
        for (int f = 0; f < 8; f++) {
            int col = base + f * 8;
            float cn0 = __ldg(&g_cnorm[col]);
            float cn1 = __ldg(&g_cnorm[col + 1]);
            float d0 = fmaf(-2.f, acc[f][0], cn0);
            float d1 = fmaf(-2.f, acc[f][1], cn1);
            float d2 = fmaf(-2.f, acc[f][2], cn0);
            float d3 = fmaf(-2.f, acc[f][3], cn1);
            if (d0 < best0) { best0 = d0; idx0 = col; }
            if (d1 < best0) { best0 = d1; idx0 = col + 1; }
            if (d2 < best1) { best1 = d2; idx1 = col; }
            if (d3 < best1) { best1 = d3; idx1 = col + 1; }
        }
    }

    // reduce across the 4 lanes sharing each row; tie -> lowest index
#pragma unroll
    for (int off = 1; off <= 2; off <<= 1) {
        float ob = __shfl_xor_sync(~0u, best0, off);
        int   oi = __shfl_xor_sync(~0u, idx0, off);
        if (ob < best0 || (ob == best0 && oi < idx0)) { best0 = ob; idx0 = oi; }
        ob = __shfl_xor_sync(~0u, best1, off);
        oi = __shfl_xor_sync(~0u, idx1, off);
        if (ob < best1 || (ob == best1 && oi < idx1)) { best1 = ob; idx1 = oi; }
    }
    if ((lane & 3) == 0) {
        int r = wid * 16 + (lane >> 2);
        idxs[r] = idx0;
        idxs[r + 8] = idx1;
        g_idx[row0 + r] = idx0;
        g_idx[row0 + r + 8] = idx1;
    }
    __syncthreads();

    // ---- in-CTA gather: quantized rows (out_q untouched by zerofill) ----
    for (int t = tid; t < BM * (DIM / 4); t += THREADS) {
        int row = t >> 4, c4 = t & 15;
        int k = idxs[row];
        reinterpret_cast<float4*>(out_q)[(size_t)(row0 + row) * 16 + c4] =
            __ldg(reinterpret_cast<const float4*>(cb + (size_t)k * DIM) + c4);
    }
}

// ---------------------------------------------------------------------------
// Finalize: scatter the 1.0s (must trail: zerofill CTAs may still be writing
// zeros while argmin CTAs finish).
// ---------------------------------------------------------------------------
__global__ void finalize_ones(float* __restrict__ out_disc) {
    unsigned n = blockIdx.x * 256u + threadIdx.x;
    out_disc[(size_t)n * N_CODES + __ldg(&g_idx[n])] = 1.0f;
}

// ---------------------------------------------------------------------------
extern "C" void kernel_launch(void* const* d_in, const int* in_sizes, int n_in,
                              void* d_out, int out_size) {
    const float* x  = (const float*)d_in[0];
    const float* cb = (const float*)d_in[1];
    float* out      = (float*)d_out;
    float* out_disc = out;
    float* out_q    = out + (size_t)N_ROWS * N_CODES;

    cudaFuncSetAttribute(argmin_fused, cudaFuncAttributeMaxDynamicSharedMemorySize, SMEMSZ);

    prep_kernel<<<(N_CODES * 32) / 256, 256>>>(cb);
    argmin_fused<<<NARG + NZERO, THREADS, SMEMSZ>>>(x, cb, out_disc, out_q);
    finalize_ones<<<N_ROWS / 256, 256>>>(out_disc);
}

// round 16
// speedup vs baseline: 1.5808x; 1.0815x over previous
#include <cuda_runtime.h>
#include <cuda_fp16.h>
#include <cstdint>

#define N_ROWS   16384
#define N_CODES  8192
#define DIM      64
#define BM       128
#define BN       64
#define NCHUNK   (N_CODES / BN)      // 128
#define THREADS  256
#define ROWB     272                  // 17*16B; 17 mod 8 = 1 -> conflict-free LDSM
#define CGSTRIDE (16 * ROWB)
#define BBUF     (BN * ROWB)          // 17408 B per B stage
#define NARG     (N_ROWS / BM)        // 128 argmin CTAs
#define NZERO    128                  // zerofill CTAs
#define DISC_F4  ((size_t)N_ROWS * N_CODES / 4)
#define OFF_IDX  (BM * ROWB + 2 * BBUF)          // 69632
#define SMEMSZ   (OFF_IDX + BM * 4)              // 70144 (x2 = 140288 < 228KB)

// device scratch: [ch(128B) | cl(128B)] per code
__device__ __align__(16) __half g_cbe[(size_t)N_CODES * 128];
__device__ __align__(16) float  g_cnorm[N_CODES];
__device__ int g_idx[N_ROWS];

// ---------------- helpers ----------------
__device__ __forceinline__ uint32_t h2_as_u32(__half2 h) {
    uint32_t u;
    __builtin_memcpy(&u, &h, 4);
    return u;
}
__device__ __forceinline__ uint32_t pack_h2(__half a, __half b) {
    return h2_as_u32(__halves2half2(a, b));
}
__device__ __forceinline__ uint32_t smem_u32(const void* p) {
    uint32_t a;
    asm("{ .reg .u64 t; cvta.to.shared.u64 t, %1; cvt.u32.u64 %0, t; }" : "=r"(a) : "l"(p));
    return a;
}
#define CPA16(d,s)   asm volatile("cp.async.cg.shared.global [%0], [%1], 16;" :: "r"(d), "l"(s) : "memory")
#define CPA_COMMIT() asm volatile("cp.async.commit_group;" ::: "memory")
#define CPA_WAIT0()  asm volatile("cp.async.wait_group 0;" ::: "memory")

#define LDM_X4(r0,r1,r2,r3,a) \
    asm volatile("ldmatrix.sync.aligned.m8n8.x4.shared.b16 {%0,%1,%2,%3}, [%4];" \
                 : "=r"(r0), "=r"(r1), "=r"(r2), "=r"(r3) : "r"(a))

__device__ __forceinline__ void mma16816(float* d, const uint32_t* a,
                                         uint32_t b0, uint32_t b1) {
    asm volatile("mma.sync.aligned.m16n8k16.row.col.f32.f16.f16.f32 "
                 "{%0,%1,%2,%3}, {%4,%5,%6,%7}, {%8,%9}, {%0,%1,%2,%3};"
                 : "+f"(d[0]), "+f"(d[1]), "+f"(d[2]), "+f"(d[3])
                 : "r"(a[0]), "r"(a[1]), "r"(a[2]), "r"(a[3]), "r"(b0), "r"(b1));
}

// ---------------------------------------------------------------------------
// Prep: codebook -> fp16 [ch|cl] + squared norms. One warp per code.
// ---------------------------------------------------------------------------
__global__ void prep_kernel(const float* __restrict__ cb) {
    int g = blockIdx.x * blockDim.x + threadIdx.x;
    int code = g >> 5, lane = g & 31;
    float2 v = reinterpret_cast<const float2*>(cb + (size_t)code * DIM)[lane];
    __half hx = __float2half_rn(v.x), hy = __float2half_rn(v.y);
    float lx = v.x - __half2float(hx), ly = v.y - __half2float(hy);
    __half2* dst = reinterpret_cast<__half2*>(g_cbe + (size_t)code * 128);
    dst[lane]      = __halves2half2(hx, hy);
    dst[32 + lane] = __halves2half2(__float2half_rn(lx), __float2half_rn(ly));
    float s = v.x * v.x + v.y * v.y;
#pragma unroll
    for (int o = 16; o; o >>= 1) s += __shfl_xor_sync(~0u, s, o);
    if (lane == 0) g_cnorm[code] = s;
}

// ---------------------------------------------------------------------------
// Fused: bid < NARG -> 8-warp mma.sync distance GEMM + argmin (R9 hot loop)
//        + in-CTA gather of quantized rows;
//        bid >= NARG -> stream zeros into the one-hot output.
// __launch_bounds__(256, 2): cap regs at 128 so argmin + zerofill CTAs
// co-reside on every SM (the single change vs R15).
// ---------------------------------------------------------------------------
__global__ void __launch_bounds__(THREADS, 2)
argmin_fused(const float* __restrict__ x, const float* __restrict__ cb,
             float* __restrict__ out_disc, float* __restrict__ out_q) {
    const int tid = threadIdx.x;

    if (blockIdx.x >= NARG) {
        size_t i = (size_t)(blockIdx.x - NARG) * THREADS + tid;
        const size_t stride = (size_t)NZERO * THREADS;
        float4 z = make_float4(0.f, 0.f, 0.f, 0.f);
        float4* o = reinterpret_cast<float4*>(out_disc);
#pragma unroll 4
        for (; i < DISC_F4; i += stride) __stcs(o + i, z);
        return;
    }

    extern __shared__ char smem[];
    const uint32_t As = smem_u32(smem);                 // [128][272] : [xh|xl]
    const uint32_t Bs = As + BM * ROWB;                 // B ring [2][17408]
    int* idxs = reinterpret_cast<int*>(smem + OFF_IDX); // [128] final indices

    const int wid = tid >> 5, lane = tid & 31;
    const int row0 = blockIdx.x * BM;

    // ---- Build A staging: row = [xh(128B) | xl(128B)] ----
    for (int t = tid; t < BM * (DIM / 4); t += THREADS) {
        int row = t >> 4, q = t & 15;
        float4 v = reinterpret_cast<const float4*>(x)[(size_t)(row0 + row) * 16 + q];
        __half h0 = __float2half_rn(v.x), h1 = __float2half_rn(v.y);
        __half h2 = __float2half_rn(v.z), h3 = __float2half_rn(v.w);
        uint32_t hp0 = pack_h2(h0, h1);
        uint32_t hp1 = pack_h2(h2, h3);
        uint32_t lp0 = pack_h2(__float2half_rn(v.x - __half2float(h0)),
                               __float2half_rn(v.y - __half2float(h1)));
        uint32_t lp1 = pack_h2(__float2half_rn(v.z - __half2float(h2)),
                               __float2half_rn(v.w - __half2float(h3)));
        uint32_t base = As + row * ROWB + q * 8;
        asm volatile("st.shared.v2.b32 [%0], {%1,%2};" :: "r"(base), "r"(hp0), "r"(hp1));
        asm volatile("st.shared.v2.b32 [%0], {%1,%2};" :: "r"(base + 128), "r"(lp0), "r"(lp1));
    }
    __syncthreads();

    // ---- Persistent A fragments: kgroups 0-3 = xh, 4-7 = xl ----
    uint32_t afr[8][4];
    {
        int t = lane >> 3;
        int arow = wid * 16 + ((t & 1) << 3) + (lane & 7);
        uint32_t abase = As + arow * ROWB + ((t >> 1) << 4);
#pragma unroll
        for (int kg = 0; kg < 8; kg++)
            LDM_X4(afr[kg][0], afr[kg][1], afr[kg][2], afr[kg][3], abase + kg * 32);
    }
    __syncthreads();

    // per-lane B ldmatrix base (16 codes x 16 k per LDM_X4)
    const uint32_t bl0 = Bs + (((lane >> 4) << 3) + (lane & 7)) * ROWB
                       + ((lane >> 3) & 1) * 16;

    // ---- prefetch chunk 0: 64 codes x 256B = 1024 x 16B ops, 4 per thread ----
    {
#pragma unroll
        for (int j = 0; j < 4; j++) {
            int i = tid + j * THREADS;
            int code = i >> 4, off = (i & 15) * 16;
            CPA16(Bs + code * ROWB + off, (const char*)g_cbe + i * 16);
        }
        CPA_COMMIT();
    }

    float best0 = 3.4e38f, best1 = 3.4e38f;
    int idx0 = 0, idx1 = 0;

    for (int c = 0; c < NCHUNK; c++) {
        CPA_WAIT0();
        __syncthreads();
        if (c + 1 < NCHUNK) {
            const char* src = (const char*)g_cbe + (size_t)(c + 1) * BN * 256;
            uint32_t dbuf = Bs + ((c + 1) & 1) * BBUF;
#pragma unroll
            for (int j = 0; j < 4; j++) {
                int i = tid + j * THREADS;
                int code = i >> 4, off = (i & 15) * 16;
                CPA16(dbuf + code * ROWB + off, src + i * 16);
            }
            CPA_COMMIT();
        }

        const uint32_t bb = bl0 + (c & 1) * BBUF;
        float acc[8][4];
#pragma unroll
        for (int f = 0; f < 8; f++)
#pragma unroll
            for (int j = 0; j < 4; j++) acc[f][j] = 0.f;

        // passes 1+2: per kgroup, load ch frags (4 LDM), sweep acc0..7 twice
#pragma unroll
        for (int t = 0; t < 4; t++) {
            uint32_t b[4][4];
#pragma unroll
            for (int cg = 0; cg < 4; cg++)
                LDM_X4(b[cg][0], b[cg][1], b[cg][2], b[cg][3],
                       bb + cg * CGSTRIDE + t * 32);
#pragma unroll
            for (int cg = 0; cg < 4; cg++) {
                mma16816(acc[2 * cg],     afr[t], b[cg][0], b[cg][1]);
                mma16816(acc[2 * cg + 1], afr[t], b[cg][2], b[cg][3]);
            }
#pragma unroll
            for (int cg = 0; cg < 4; cg++) {
                mma16816(acc[2 * cg],     afr[4 + t], b[cg][0], b[cg][1]);
                mma16816(acc[2 * cg + 1], afr[4 + t], b[cg][2], b[cg][3]);
            }
        }
        // pass 3: xh . cl
#pragma unroll
        for (int t = 0; t < 4; t++) {
            uint32_t b[4][4];
#pragma unroll
            for (int cg = 0; cg < 4; cg++)
                LDM_X4(b[cg][0], b[cg][1], b[cg][2], b[cg][3],
                       bb + 128 + cg * CGSTRIDE + t * 32);
#pragma unroll
            for (int cg = 0; cg < 4; cg++) {
                mma16816(acc[2 * cg],     afr[t], b[cg][0], b[cg][1]);
                mma16816(acc[2 * cg + 1], afr[t], b[cg][2], b[cg][3]);
            }
        }

        int base = c * BN + ((lane & 3) << 1);
#pragma unroll
        for (int f = 0; f < 8; f++) {
            int col = base + f * 8;
            float cn0 = __ldg(&g_cnorm[col]);
            float cn1 = __ldg(&g_cnorm[col + 1]);
            float d0 = fmaf(-2.f, acc[f][0], cn0);
            float d1 = fmaf(-2.f, acc[f][1], cn1);
            float d2 = fmaf(-2.f, acc[f][2], cn0);
            float d3 = fmaf(-2.f, acc[f][3], cn1);
            if (d0 < best0) { best0 = d0; idx0 = col; }
            if (d1 < best0) { best0 = d1; idx0 = col + 1; }
            if (d2 < best1) { best1 = d2; idx1 = col; }
            if (d3 < best1) { best1 = d3; idx1 = col + 1; }
        }
    }

    // reduce across the 4 lanes sharing each row; tie -> lowest index
#pragma unroll
    for (int off = 1; off <= 2; off <<= 1) {
        float ob = __shfl_xor_sync(~0u, best0, off);
        int   oi = __shfl_xor_sync(~0u, idx0, off);
        if (ob < best0 || (ob == best0 && oi < idx0)) { best0 = ob; idx0 = oi; }
        ob = __shfl_xor_sync(~0u, best1, off);
        oi = __shfl_xor_sync(~0u, idx1, off);
        if (ob < best1 || (ob == best1 && oi < idx1)) { best1 = ob; idx1 = oi; }
    }
    if ((lane & 3) == 0) {
        int r = wid * 16 + (lane >> 2);
        idxs[r] = idx0;
        idxs[r + 8] = idx1;
        g_idx[row0 + r] = idx0;
        g_idx[row0 + r + 8] = idx1;
    }
    __syncthreads();

    // ---- in-CTA gather: quantized rows (out_q untouched by zerofill) ----
    for (int t = tid; t < BM * (DIM / 4); t += THREADS) {
        int row = t >> 4, c4 = t & 15;
        int k = idxs[row];
        reinterpret_cast<float4*>(out_q)[(size_t)(row0 + row) * 16 + c4] =
            __ldg(reinterpret_cast<const float4*>(cb + (size_t)k * DIM) + c4);
    }
}

// ---------------------------------------------------------------------------
// Finalize: scatter the 1.0s (must trail: zerofill CTAs may still be writing
// zeros while argmin CTAs finish).
// ---------------------------------------------------------------------------
__global__ void finalize_ones(float* __restrict__ out_disc) {
    unsigned n = blockIdx.x * 256u + threadIdx.x;
    out_disc[(size_t)n * N_CODES + __ldg(&g_idx[n])] = 1.0f;
}

// ---------------------------------------------------------------------------
extern "C" void kernel_launch(void* const* d_in, const int* in_sizes, int n_in,
                              void* d_out, int out_size) {
    const float* x  = (const float*)d_in[0];
    const float* cb = (const float*)d_in[1];
    float* out      = (float*)d_out;
    float* out_disc = out;
    float* out_q    = out + (size_t)N_ROWS * N_CODES;

    cudaFuncSetAttribute(argmin_fused, cudaFuncAttributeMaxDynamicSharedMemorySize, SMEMSZ);

    prep_kernel<<<(N_CODES * 32) / 256, 256>>>(cb);
    argmin_fused<<<NARG + NZERO, THREADS, SMEMSZ>>>(x, cb, out_disc, out_q);
    finalize_ones<<<N_ROWS / 256, 256>>>(out_disc);
}